// round 7
// baseline (speedup 1.0000x reference)
#include <cuda_runtime.h>
#include <cuda_fp16.h>
#include <cstdint>

#define NTOT 16384
#define KN   16
#define NP   15
#define CIN  64
#define COUT 128
#define KTOT (NP * CIN)        // 960

// ---------------- global scratch (allowed: __device__ arrays) ----------------
__device__ __half g_A[(size_t)NTOT * KTOT];     // [n][k] k-major, fp16
__device__ __half g_Bhi[COUT * KTOT];           // [cout][k] k-major (= W^T) hi
__device__ __half g_Blo[COUT * KTOT];           // residual lo

typedef unsigned long long u64;
typedef unsigned int u32;

__device__ __forceinline__ u64 pack2(float lo, float hi) {
    u64 r; asm("mov.b64 %0, {%1, %2};" : "=l"(r) : "f"(lo), "f"(hi)); return r;
}
__device__ __forceinline__ void unpack2(u64 v, float &lo, float &hi) {
    asm("mov.b64 {%0, %1}, %2;" : "=f"(lo), "=f"(hi) : "l"(v));
}
__device__ __forceinline__ void fma2(u64 &d, u64 a, u64 b) {
    asm("fma.rn.f32x2 %0, %1, %2, %3;" : "=l"(d) : "l"(a), "l"(b), "l"(d));
}
__device__ __forceinline__ u32 h2pk(float a, float b) {
    __half ha = __float2half_rn(a), hb = __float2half_rn(b);
    unsigned short ua = *reinterpret_cast<unsigned short*>(&ha);
    unsigned short ub = *reinterpret_cast<unsigned short*>(&hb);
    return (u32)ua | ((u32)ub << 16);
}
__device__ __forceinline__ u32 smem_u32(const void* p) {
    u32 a; asm("{ .reg .u64 t; cvta.to.shared.u64 t, %1; cvt.u32.u64 %0, t; }"
               : "=r"(a) : "l"(p));
    return a;
}
__device__ __forceinline__ void ldmx4(u32* r, u32 addr) {
    asm volatile("ldmatrix.sync.aligned.m8n8.x4.shared.b16 {%0,%1,%2,%3}, [%4];"
                 : "=r"(r[0]), "=r"(r[1]), "=r"(r[2]), "=r"(r[3]) : "r"(addr));
}
__device__ __forceinline__ void mma_f16(float* d, const u32* a, const u32* b) {
    asm volatile("mma.sync.aligned.m16n8k16.row.col.f32.f16.f16.f32 "
                 "{%0,%1,%2,%3}, {%4,%5,%6,%7}, {%8,%9}, {%0,%1,%2,%3};"
                 : "+f"(d[0]), "+f"(d[1]), "+f"(d[2]), "+f"(d[3])
                 : "r"(a[0]), "r"(a[1]), "r"(a[2]), "r"(a[3]),
                   "r"(b[0]), "r"(b[1]));
}

// ====== kernel 1: gather + influence + aggregation (+ fused W-split) ======
// warp-per-query: 8 queries/CTA, 256 threads; lane owns 2 channels.
#define Q1 8
#define NT1 256
__global__ __launch_bounds__(NT1)
void k1_agg(const float* __restrict__ query,
            const float* __restrict__ support,
            const int*   __restrict__ nidx,
            const float* __restrict__ feats,
            const float* __restrict__ kp,
            const float* __restrict__ W)
{
    __shared__ float s_infl[Q1 * KN * 16];
    __shared__ float s_kp[48];
    __shared__ float s_q[Q1 * 3];
    __shared__ int   s_nidx[Q1 * KN];

    const int tid = threadIdx.x;
    const int n0  = blockIdx.x * Q1;

    if (tid < Q1 * KN)  s_nidx[tid] = nidx[n0 * KN + tid];
    if (tid < NP * 3)   s_kp[tid]   = kp[tid];
    if (tid < Q1 * 3)   s_q[tid]    = query[n0 * 3 + tid];
    __syncthreads();

    // influences: one (q,k) pair per thread (128 pairs)
    if (tid < Q1 * KN) {
        int pair = tid;
        int qq = pair >> 4;
        int m  = s_nidx[pair];
        float rx = support[m * 3 + 0] - s_q[qq * 3 + 0];
        float ry = support[m * 3 + 1] - s_q[qq * 3 + 1];
        float rz = support[m * 3 + 2] - s_q[qq * 3 + 2];
        #pragma unroll
        for (int p = 0; p < NP; p++) {
            float dx = rx - s_kp[p * 3 + 0];
            float dy = ry - s_kp[p * 3 + 1];
            float dz = rz - s_kp[p * 3 + 2];
            float d  = sqrtf(fmaf(dx, dx, fmaf(dy, dy, dz * dz)));
            s_infl[pair * 16 + p] = fmaxf(1.0f - d, 0.0f);
        }
        s_infl[pair * 16 + 15] = 0.0f;
    }
    __syncthreads();

    const int q    = tid >> 5;          // warp id = query
    const int lane = tid & 31;
    const int ch   = lane << 1;         // 2 channels per lane

    u64 acc[NP];
    #pragma unroll
    for (int p = 0; p < NP; p++) acc[p] = 0ULL;

    #pragma unroll
    for (int k = 0; k < KN; k++) {
        int m = s_nidx[q * KN + k];
        float2 f = __ldg((const float2*)(feats + (size_t)m * CIN + ch));
        u64 fx = pack2(f.x, f.y);
        const float* ib = s_infl + (q * KN + k) * 16;   // warp-uniform
        float4 i0 = *(const float4*)(ib + 0);
        float4 i1 = *(const float4*)(ib + 4);
        float4 i2 = *(const float4*)(ib + 8);
        float4 i3 = *(const float4*)(ib + 12);
        float iv[16] = { i0.x,i0.y,i0.z,i0.w, i1.x,i1.y,i1.z,i1.w,
                         i2.x,i2.y,i2.z,i2.w, i3.x,i3.y,i3.z,i3.w };
        #pragma unroll
        for (int p = 0; p < NP; p++)
            fma2(acc[p], pack2(iv[p], iv[p]), fx);
    }

    // store A as fp16 (2 channels -> one u32 per p; warp = 128B contiguous)
    const size_t rowbase = (size_t)(n0 + q) * KTOT + ch;
    #pragma unroll
    for (int p = 0; p < NP; p++) {
        float a0, a1;
        unpack2(acc[p], a0, a1);
        *(u32*)(g_A + rowbase + p * CIN) = h2pk(a0, a1);
    }

    // ---- fused W-split: blocks 0..119 convert W -> Bhi/Blo fp16 ----
    if (blockIdx.x < 120) {
        int idx4 = blockIdx.x * NT1 + tid;     // 0..30719, 4 k-elems each
        int n  = idx4 / 240;
        int kq = idx4 - n * 240;
        int k  = kq * 4;
        int p  = k >> 6, cin = k & 63;
        const float* wp = W + p * CIN * COUT + cin * COUT + n;
        float w0 = __ldg(wp);
        float w1 = __ldg(wp + COUT);
        float w2 = __ldg(wp + 2 * COUT);
        float w3 = __ldg(wp + 3 * COUT);
        __half h0 = __float2half_rn(w0), h1 = __float2half_rn(w1);
        __half h2 = __float2half_rn(w2), h3 = __float2half_rn(w3);
        float l0 = w0 - __half2float(h0), l1 = w1 - __half2float(h1);
        float l2 = w2 - __half2float(h2), l3 = w3 - __half2float(h3);
        unsigned short u0 = *reinterpret_cast<unsigned short*>(&h0);
        unsigned short u1 = *reinterpret_cast<unsigned short*>(&h1);
        unsigned short u2 = *reinterpret_cast<unsigned short*>(&h2);
        unsigned short u3 = *reinterpret_cast<unsigned short*>(&h3);
        uint2 vh = make_uint2((u32)u0 | ((u32)u1 << 16), (u32)u2 | ((u32)u3 << 16));
        uint2 vl = make_uint2(h2pk(l0, l1), h2pk(l2, l3));
        *(uint2*)(g_Bhi + (size_t)n * KTOT + k) = vh;
        *(uint2*)(g_Blo + (size_t)n * KTOT + k) = vl;
    }
}

// ================= kernel 2: mma.sync fp16 x2 GEMM =================
// D[16384 x 128] = A*(Bhi+Blo) ; M-tile 128, N=128, K=960.
// 512 threads: 16 warps in 4(M) x 4(N); each warp 32x32.
// smem: 2 buffers x 3 tiles x [128 rows x 128B] = 98304 bytes.
#define NT2 512
#define NCHUNK 15
#define TILEB 16384
#define BUFB  (3 * TILEB)

__global__ __launch_bounds__(NT2, 1)
void k2_gemm(float* __restrict__ out)
{
    extern __shared__ char smem[];
    const u32 sb = smem_u32(smem);
    const int tid  = threadIdx.x;
    const int wid  = tid >> 5;
    const int lane = tid & 31;
    const int wm   = wid >> 2;       // 0..3  (M groups of 32)
    const int wn   = wid & 3;        // 0..3  (N groups of 32)
    const int m0   = blockIdx.x * 128;

    const __half* srcs[3] = { g_A, g_Bhi, g_Blo };

    // ldmatrix per-thread addressing (swizzle: row*128 + (o ^ (row&7)*16))
    const int a_row  = wm * 32 + (lane & 7) + ((lane >> 3) & 1) * 8;  // + mi*16
    const int a_bh   = ((lane >> 4) & 1) * 16;
    const u32 a_mask = (u32)((a_row & 7) * 16);
    const int b_row  = wn * 32 + (lane & 7) + ((lane >> 4) & 1) * 8;  // + nj*16
    const int b_bh   = ((lane >> 3) & 1) * 16;
    const u32 b_mask = (u32)((b_row & 7) * 16);

    float acc[2][4][4];
    #pragma unroll
    for (int mi = 0; mi < 2; mi++)
        #pragma unroll
        for (int ni = 0; ni < 4; ni++)
            #pragma unroll
            for (int e = 0; e < 4; e++) acc[mi][ni][e] = 0.0f;

    // ---- async load of one chunk into buffer (c&1): 3 tiles ----
    auto load_chunk = [&](int c) {
        u32 dstb = sb + (u32)(c & 1) * BUFB;
        #pragma unroll
        for (int j = 0; j < 6; j++) {
            int idx = tid + j * NT2;              // 0..3071
            int t    = idx >> 10;                 // 0:A 1:Bhi 2:Blo
            int win  = idx & 1023;
            int row  = win >> 3;
            int c16  = win & 7;
            int rb   = (t == 0) ? m0 : 0;
            const __half* src = srcs[t] + (size_t)(rb + row) * KTOT
                                + c * 64 + c16 * 8;
            u32 dst = dstb + (u32)t * TILEB
                    + (u32)(row * 128 + ((c16 * 16) ^ ((row & 7) * 16)));
            asm volatile("cp.async.cg.shared.global [%0], [%1], 16;"
                         :: "r"(dst), "l"(src) : "memory");
        }
        asm volatile("cp.async.commit_group;" ::: "memory");
    };

    load_chunk(0);

    for (int c = 0; c < NCHUNK; c++) {
        if (c + 1 < NCHUNK) {
            load_chunk(c + 1);
            asm volatile("cp.async.wait_group 1;" ::: "memory");
        } else {
            asm volatile("cp.async.wait_group 0;" ::: "memory");
        }
        __syncthreads();

        const u32 bufb = sb + (u32)(c & 1) * BUFB;
        const u32 aBase   = bufb + (u32)(a_row * 128);
        const u32 bHiBase = bufb + TILEB + (u32)(b_row * 128);

        #pragma unroll
        for (int ks = 0; ks < 4; ks++) {
            const u32 aOff = (u32)((ks * 32 + a_bh)) ^ a_mask;
            const u32 bOff = (u32)((ks * 32 + b_bh)) ^ b_mask;

            u32 bhi[8], blo[8];
            #pragma unroll
            for (int nj = 0; nj < 2; nj++) {
                u32 ba = bHiBase + (u32)(nj * 16 * 128) + bOff;
                ldmx4(&bhi[nj * 4], ba);
                ldmx4(&blo[nj * 4], ba + TILEB);
            }
            #pragma unroll
            for (int mi = 0; mi < 2; mi++) {
                u32 a[4];
                ldmx4(a, aBase + (u32)(mi * 16 * 128) + aOff);
                #pragma unroll
                for (int ni = 0; ni < 4; ni++)
                    mma_f16(acc[mi][ni], a, &bhi[(ni >> 1) * 4 + (ni & 1) * 2]);
                #pragma unroll
                for (int ni = 0; ni < 4; ni++)
                    mma_f16(acc[mi][ni], a, &blo[(ni >> 1) * 4 + (ni & 1) * 2]);
            }
        }
        __syncthreads();
    }

    // ---- epilogue ----
    #pragma unroll
    for (int mi = 0; mi < 2; mi++) {
        int row = m0 + wm * 32 + mi * 16 + (lane >> 2);
        #pragma unroll
        for (int ni = 0; ni < 4; ni++) {
            int col = wn * 32 + ni * 8 + (lane & 3) * 2;
            *(float2*)(out + (size_t)row * COUT + col) =
                make_float2(acc[mi][ni][0], acc[mi][ni][1]);
            *(float2*)(out + (size_t)(row + 8) * COUT + col) =
                make_float2(acc[mi][ni][2], acc[mi][ni][3]);
        }
    }
}

// ================= launch =================
extern "C" void kernel_launch(void* const* d_in, const int* in_sizes, int n_in,
                              void* d_out, int out_size) {
    const float* query   = (const float*)d_in[0];
    const float* support = (const float*)d_in[1];
    const int*   nidx    = (const int*)d_in[2];
    const float* feats   = (const float*)d_in[3];
    const float* W       = (const float*)d_in[4];
    const float* kp      = (const float*)d_in[5];
    float* out = (float*)d_out;

    k1_agg<<<NTOT / Q1, NT1>>>(query, support, nidx, feats, kp, W);

    const int smem2 = 2 * BUFB;   // 98304
    cudaFuncSetAttribute(k2_gemm, cudaFuncAttributeMaxDynamicSharedMemorySize, smem2);
    k2_gemm<<<NTOT / 128, NT2, smem2>>>(out);
}